// round 9
// baseline (speedup 1.0000x reference)
#include <cuda_runtime.h>
#include <cstdint>

// FlowNetC correlation: out[b, (dy+4)*9+(dx+4), y, x] =
//   (1/C) * sum_c in1[b,c,y,x] * in2[b,c,y+dy,x+dx], zero-padded.
// Shapes: in1,in2 [8,256,96,128] f32; out [8,81,96,128] f32.
//
// Block = (3 dy values) x (4 output rows) x batch. 128 threads, warp = row,
// lane -> 4 consecutive x. Packed fma.rn.f32x2 (2 pixels per FMA).
// in2 staged with cp.async into a double-buffered 6-row window.
//
// BUGFIX vs R7/R8: compute reads from smem base xx = x0 (NOT 4+x0).
// s[xx] holds in2 column x = xx-4; pixel x0+i at displacement d needs
// xx = x0+i+d, i in 0..3, d in 0..8 -> xx in [x0, x0+11], max 135 < 136.
// The former +4 base both shifted results and read out of bounds.

#define B_   8
#define C_   256
#define H_   96
#define W_   128
#define HW_  (H_ * W_)
#define CC   4      // channels per chunk
#define RWS  4      // output rows per block
#define SR   6      // staged in2 rows per buffer (RWS + 2 halo for 3 dy)
#define W2   136    // padded row: xx = x + 4, x in [-4, 131]

typedef unsigned long long ull;

__device__ __forceinline__ ull pk2(float lo, float hi) {
    ull r;
    asm("mov.b64 %0, {%1, %2};" : "=l"(r) : "f"(lo), "f"(hi));
    return r;
}
__device__ __forceinline__ void fma2(ull& d, ull a, ull b) {
    asm("fma.rn.f32x2 %0, %1, %2, %0;" : "+l"(d) : "l"(a), "l"(b));
}
__device__ __forceinline__ float2 upk(ull v) {
    float2 f;
    asm("mov.b64 {%0, %1}, %2;" : "=f"(f.x), "=f"(f.y) : "l"(v));
    return f;
}

__device__ __forceinline__ void cp16(uint32_t sdst, ull gsrc, int srcsz) {
    asm volatile("cp.async.cg.shared.global [%0], [%1], 16, %2;"
                 :: "r"(sdst), "l"(gsrc), "r"(srcsz) : "memory");
}

__global__ __launch_bounds__(128, 3) void corr_kernel(
    const float* __restrict__ in1,
    const float* __restrict__ in2,
    float* __restrict__ out)
{
    __shared__ float s2[2][CC][SR][W2];   // 26112 B

    const int dyg  = blockIdx.x;          // 0..2  -> dy = 3*dyg-4 + {0,1,2}
    const int y0   = blockIdx.y * RWS;
    const int b    = blockIdx.z;
    const int tid  = threadIdx.x;
    const int wid  = tid >> 5;            // 0..3 = output row in tile
    const int lane = tid & 31;
    const int x0   = lane << 2;           // 0..124
    const int d0   = dyg * 3 - 4;

    // Zero left/right x-pads once (staging never writes xx<4 or xx>=132).
    if (tid < 2 * CC * SR) {
        float* row = &s2[0][0][0][0] + tid * W2;
#pragma unroll
        for (int j = 0; j < 4; j++) { row[j] = 0.0f; row[132 + j] = 0.0f; }
    }

    // ---- staging setup: warp wid stages channel (c0+wid), rows j=0..5 ----
    // staged row j holds in2 row (y0 + d0 + j), zero-filled if out of range.
    ull st_src = (ull)__cvta_generic_to_global(
                     in2 + ((long)(b * C_) + wid) * HW_ + x0);
    ull roff[SR];
    int rsz[SR];
#pragma unroll
    for (int j = 0; j < SR; j++) {
        int y2 = y0 + d0 + j;
        int yc = y2 < 0 ? 0 : (y2 > H_ - 1 ? H_ - 1 : y2);
        roff[j] = (ull)(yc * W_) * sizeof(float);
        rsz[j]  = ((unsigned)y2 < (unsigned)H_) ? 16 : 0;
    }
    const uint32_t st_dst =
        (uint32_t)__cvta_generic_to_shared(&s2[0][wid][0][4 + x0]);
    const uint32_t ROWB = W2 * 4;                 // 544
    const uint32_t BUFB = CC * SR * W2 * 4;       // 13056
    const ull      CHB  = (ull)CC * HW_ * sizeof(float);

#define STAGE(dstbase, srcb)                                                  \
    {                                                                         \
        _Pragma("unroll")                                                     \
        for (int j = 0; j < SR; j++)                                          \
            cp16((dstbase) + j * ROWB, (srcb) + roff[j], rsz[j]);             \
        asm volatile("cp.async.commit_group;" ::: "memory");                  \
    }

    // ---- prologue: chunk 0 -> buffer 0 ----
    STAGE(st_dst, st_src);
    asm volatile("cp.async.wait_group 0;" ::: "memory");
    __syncthreads();

    ull acc[3][2][9];
#pragma unroll
    for (int l = 0; l < 3; l++)
#pragma unroll
        for (int p = 0; p < 2; p++)
#pragma unroll
            for (int d = 0; d < 9; d++) acc[l][p][d] = 0ull;

    const float* a_run  = in1 + ((long)(b * C_)) * HW_
                              + (long)(y0 + wid) * W_ + x0;
    ull st_run = st_src + CHB;
    int buf = 0;

    for (int c0 = 0; c0 < C_; c0 += CC) {
        const bool has_next = (c0 + CC < C_);
        if (has_next) {
            STAGE(st_dst + (uint32_t)(buf ^ 1) * BUFB, st_run);
            st_run += CHB;
        }

        const float(*sb)[SR][W2] = s2[buf];
#pragma unroll
        for (int cc = 0; cc < CC; cc++) {
            float4 a = *reinterpret_cast<const float4*>(a_run + (long)cc * HW_);
            ull ap0 = pk2(a.x, a.y);     // pixels (0,1)
            ull ap1 = pk2(a.z, a.w);     // pixels (2,3)
#pragma unroll
            for (int dyl = 0; dyl < 3; dyl++) {
                // Correct base: xx = x0 (w[k] = in2 column x0+k-4).
                const float* sr = &sb[cc][wid + dyl][x0];   // 16B aligned
                float4 w0 = *reinterpret_cast<const float4*>(sr);
                float4 w1 = *reinterpret_cast<const float4*>(sr + 4);
                float4 w2 = *reinterpret_cast<const float4*>(sr + 8);
                // even pairs (aligned float4 sub-pairs)
                ull e0 = pk2(w0.x, w0.y), e1 = pk2(w0.z, w0.w);
                ull e2 = pk2(w1.x, w1.y), e3 = pk2(w1.z, w1.w);
                ull e4 = pk2(w2.x, w2.y), e5 = pk2(w2.z, w2.w);
                // odd pairs (w[2j+1], w[2j+2])
                ull o0 = pk2(w0.y, w0.z), o1 = pk2(w0.w, w1.x);
                ull o2 = pk2(w1.y, w1.z), o3 = pk2(w1.w, w2.x);
                ull o4 = pk2(w2.y, w2.z);
                // pixel pair (0,1): b = (w[d], w[d+1])
                fma2(acc[dyl][0][0], ap0, e0);
                fma2(acc[dyl][0][1], ap0, o0);
                fma2(acc[dyl][0][2], ap0, e1);
                fma2(acc[dyl][0][3], ap0, o1);
                fma2(acc[dyl][0][4], ap0, e2);
                fma2(acc[dyl][0][5], ap0, o2);
                fma2(acc[dyl][0][6], ap0, e3);
                fma2(acc[dyl][0][7], ap0, o3);
                fma2(acc[dyl][0][8], ap0, e4);
                // pixel pair (2,3): b = (w[d+2], w[d+3])
                fma2(acc[dyl][1][0], ap1, e1);
                fma2(acc[dyl][1][1], ap1, o1);
                fma2(acc[dyl][1][2], ap1, e2);
                fma2(acc[dyl][1][3], ap1, o2);
                fma2(acc[dyl][1][4], ap1, e3);
                fma2(acc[dyl][1][5], ap1, o3);
                fma2(acc[dyl][1][6], ap1, e4);
                fma2(acc[dyl][1][7], ap1, o4);
                fma2(acc[dyl][1][8], ap1, e5);
            }
        }
        a_run += (long)CC * HW_;

        if (has_next)
            asm volatile("cp.async.wait_group 0;" ::: "memory");
        __syncthreads();
        buf ^= 1;
    }

    // ---- epilogue: 27 float4 stores ----
    const float sc = 1.0f / (float)C_;
    float* ob = out + (((long)b * 81 + dyg * 27) * H_ + (y0 + wid)) * (long)W_ + x0;
#pragma unroll
    for (int dyl = 0; dyl < 3; dyl++)
#pragma unroll
        for (int d = 0; d < 9; d++) {
            float2 lo = upk(acc[dyl][0][d]);
            float2 hi = upk(acc[dyl][1][d]);
            float4 v = make_float4(lo.x * sc, lo.y * sc, hi.x * sc, hi.y * sc);
            *reinterpret_cast<float4*>(ob + (long)(dyl * 9 + d) * HW_) = v;
        }
}

extern "C" void kernel_launch(void* const* d_in, const int* in_sizes, int n_in,
                              void* d_out, int out_size)
{
    const float* in1 = (const float*)d_in[0];
    const float* in2 = (const float*)d_in[1];
    float* out = (float*)d_out;

    dim3 grid(3, H_ / RWS, B_);   // dy-group, y-tiles, batch
    dim3 block(128);
    corr_kernel<<<grid, block>>>(in1, in2, out);
}

// round 10
// speedup vs baseline: 1.5919x; 1.5919x over previous
#include <cuda_runtime.h>
#include <cstdint>

// FlowNetC correlation: out[b, (dy+4)*9+(dx+4), y, x] =
//   (1/C) * sum_c in1[b,c,y,x] * in2[b,c,y+dy,x+dx], zero-padded.
// Shapes: in1,in2 [8,256,96,128] f32; out [8,81,96,128] f32.
//
// Block = ONE output row (y0, b); 288 threads = 9 warps; warp w computes
// dy = w-4 for the whole row (4 px per lane, 9 dx in registers).
// in1 row + 9-row in2 window staged ONCE per channel chunk and shared by
// all 9 dy-warps -> L2 input traffic ~7.5x lower than one-dy-per-block.
// Plain FFMA (f32x2 regressed in R9: pack MOVs + register pressure).
// All cp.async staging jobs precomputed per thread (5 jobs, fixed stride).

#define B_   8
#define C_   256
#define H_   96
#define W_   128
#define HW_  (H_ * W_)
#define CC   4            // channels per chunk
#define NDY  9            // dy values = warps per block
#define W2   136          // padded in2 row: xx = x+4, x in [-4,131]
#define NTHR 288
#define NJOB (128 + CC * NDY * 34)   // 128 in1-segs + 1224 in2-segs = 1352
#define KMAX 5                        // ceil(1352/288)

typedef unsigned long long ull;

__device__ __forceinline__ void cp16(uint32_t sdst, ull gsrc, int srcsz) {
    asm volatile("cp.async.cg.shared.global [%0], [%1], 16, %2;"
                 :: "r"(sdst), "l"(gsrc), "r"(srcsz) : "memory");
}

__global__ __launch_bounds__(NTHR, 2) void corr_kernel(
    const float* __restrict__ in1,
    const float* __restrict__ in2,
    float* __restrict__ out)
{
    __shared__ float s1[2][CC][W_];        // in1 row tile: 4096 B
    __shared__ float s2[2][CC][NDY][W2];   // in2 window:  39168 B

    const int y0   = blockIdx.x;           // output row
    const int b    = blockIdx.y;
    const int tid  = threadIdx.x;
    const int wid  = tid >> 5;             // dy index 0..8 (dy = wid-4)
    const int lane = tid & 31;
    const int x0   = lane << 2;            // 0..124

    // ---- precompute staging jobs (16B cp.async each) ----
    // job idx < 128:    in1 row y0, channel cc=idx>>5, 16B segment idx&31
    // job idx >= 128:   in2: cc = j/306, window row r = (j%306)/34 (in2 row
    //                   y0+r-4, clamped), segment seg = j%34 over 136 floats
    //                   (seg 0 and 33 are the x-pads -> zero-fill via rsz=0)
    ull      g0[KMAX];
    uint32_t sA[KMAX], sB[KMAX];
    int      rs[KMAX];                     // 16 = copy, 0 = zero-fill, -1 = skip
#pragma unroll
    for (int k = 0; k < KMAX; k++) {
        int idx = tid + k * NTHR;
        if (idx >= NJOB) { rs[k] = -1; g0[k] = 0; sA[k] = sB[k] = 0; continue; }
        if (idx < 128) {
            int cc = idx >> 5, seg = idx & 31;
            g0[k] = (ull)__cvta_generic_to_global(
                        in1 + ((long)(b * C_) + cc) * HW_ + (long)y0 * W_ + seg * 4);
            sA[k] = (uint32_t)__cvta_generic_to_shared(&s1[0][cc][seg * 4]);
            sB[k] = (uint32_t)__cvta_generic_to_shared(&s1[1][cc][seg * 4]);
            rs[k] = 16;
        } else {
            int j   = idx - 128;
            int cc  = j / (NDY * 34);
            int rem = j - cc * (NDY * 34);
            int r   = rem / 34;
            int seg = rem - r * 34;
            int y2  = y0 + r - 4;
            int yc  = y2 < 0 ? 0 : (y2 > H_ - 1 ? H_ - 1 : y2);
            bool ok = ((unsigned)y2 < (unsigned)H_) && seg >= 1 && seg <= 32;
            int gx  = (seg >= 1) ? (seg - 1) * 4 : 0;   // global float offset
            g0[k] = (ull)__cvta_generic_to_global(
                        in2 + ((long)(b * C_) + cc) * HW_ + (long)yc * W_ + gx);
            sA[k] = (uint32_t)__cvta_generic_to_shared(&s2[0][cc][r][seg * 4]);
            sB[k] = (uint32_t)__cvta_generic_to_shared(&s2[1][cc][r][seg * 4]);
            rs[k] = ok ? 16 : 0;
        }
    }
    const ull CHB = (ull)CC * HW_ * sizeof(float);   // per-chunk source stride

#define STAGE(bufsel)                                                         \
    {                                                                         \
        _Pragma("unroll")                                                     \
        for (int k = 0; k < KMAX; k++)                                        \
            if (rs[k] >= 0)                                                   \
                cp16((bufsel) ? sB[k] : sA[k], g0[k], rs[k]);                 \
        asm volatile("cp.async.commit_group;" ::: "memory");                  \
        _Pragma("unroll")                                                     \
        for (int k = 0; k < KMAX; k++) g0[k] += CHB;                          \
    }

    // ---- prologue: chunk 0 -> buffer 0 ----
    STAGE(0);
    asm volatile("cp.async.wait_group 0;" ::: "memory");
    __syncthreads();

    float acc[NDY][4];                     // [dx][px]
#pragma unroll
    for (int d = 0; d < NDY; d++)
#pragma unroll
        for (int i = 0; i < 4; i++) acc[d][i] = 0.0f;

    int buf = 0;
    for (int c0 = 0; c0 < C_; c0 += CC) {
        const bool has_next = (c0 + CC < C_);
        if (has_next) STAGE(buf ^ 1);

#pragma unroll
        for (int cc = 0; cc < CC; cc++) {
            float4 a = *reinterpret_cast<const float4*>(&s1[buf][cc][x0]);
            const float* sr = &s2[buf][cc][wid][x0];       // 16B aligned
            float4 w0 = *reinterpret_cast<const float4*>(sr);
            float4 w1 = *reinterpret_cast<const float4*>(sr + 4);
            float4 w2 = *reinterpret_cast<const float4*>(sr + 8);
            float wv[12] = {w0.x, w0.y, w0.z, w0.w,
                            w1.x, w1.y, w1.z, w1.w,
                            w2.x, w2.y, w2.z, w2.w};
            float av[4] = {a.x, a.y, a.z, a.w};
#pragma unroll
            for (int d = 0; d < NDY; d++)
#pragma unroll
                for (int i = 0; i < 4; i++)
                    acc[d][i] = fmaf(av[i], wv[i + d], acc[d][i]);
        }

        if (has_next)
            asm volatile("cp.async.wait_group 0;" ::: "memory");
        __syncthreads();
        buf ^= 1;
    }

    // ---- epilogue: 9 float4 stores (channels wid*9 .. wid*9+8) ----
    const float sc = 1.0f / (float)C_;
    float* ob = out + (((long)b * 81 + wid * NDY) * H_ + y0) * (long)W_ + x0;
#pragma unroll
    for (int d = 0; d < NDY; d++) {
        float4 v = make_float4(acc[d][0] * sc, acc[d][1] * sc,
                               acc[d][2] * sc, acc[d][3] * sc);
        *reinterpret_cast<float4*>(ob + (long)d * HW_) = v;
    }
}

extern "C" void kernel_launch(void* const* d_in, const int* in_sizes, int n_in,
                              void* d_out, int out_size)
{
    const float* in1 = (const float*)d_in[0];
    const float* in2 = (const float*)d_in[1];
    float* out = (float*)d_out;

    dim3 grid(H_, B_);     // one block per (output row, batch)
    dim3 block(NTHR);      // 9 warps: warp = dy
    corr_kernel<<<grid, block>>>(in1, in2, out);
}

// round 11
// speedup vs baseline: 1.6481x; 1.0353x over previous
#include <cuda_runtime.h>
#include <cstdint>

// FlowNetC correlation: out[b, (dy+4)*9+(dx+4), y, x] =
//   (1/C) * sum_c in1[b,c,y,x] * in2[b,c,y+dy,x+dx], zero-padded.
// Shapes: in1,in2 [8,256,96,128] f32; out [8,81,96,128] f32.
//
// Block = one output row (y0, b); 288 threads = 9 warps; warp w <-> dy=w-4.
// in2 9-row window staged once per channel chunk (shared by all 9 dy-warps);
// in1 read per-warp via LDG.128 -> warps 1..8 hit L1 (no smem, no extra L2).
// Staging map is trivial: warp w stages window row w, lane l stages 16B at
// xx = 4+4l (one cp.async per thread per channel, zero index math).

#define B_   8
#define C_   256
#define H_   96
#define W_   128
#define HW_  (H_ * W_)
#define CC   4            // channels per chunk
#define NDY  9            // dy values = warps per block
#define W2   136          // padded in2 row: xx = x+4, x in [-4,131]
#define NTHR 288

typedef unsigned long long ull;

__device__ __forceinline__ void cp16(uint32_t sdst, ull gsrc, int srcsz) {
    asm volatile("cp.async.cg.shared.global [%0], [%1], 16, %2;"
                 :: "r"(sdst), "l"(gsrc), "r"(srcsz) : "memory");
}

__global__ __launch_bounds__(NTHR, 3) void corr_kernel(
    const float* __restrict__ in1,
    const float* __restrict__ in2,
    float* __restrict__ out)
{
    __shared__ float s2[2][CC][NDY][W2];   // 39168 B

    const int y0   = blockIdx.x;           // output row
    const int b    = blockIdx.y;
    const int tid  = threadIdx.x;
    const int wid  = tid >> 5;             // dy index 0..8 (dy = wid-4)
    const int lane = tid & 31;
    const int x0   = lane << 2;            // 0..124

    // Zero the x-pads once (staging never writes xx<4 or xx>=132).
    if (tid < 2 * CC * NDY) {
        float* row = &s2[0][0][0][0] + tid * W2;
#pragma unroll
        for (int j = 0; j < 4; j++) { row[j] = 0.0f; row[132 + j] = 0.0f; }
    }

    // ---- staging: warp wid stages window row wid (in2 row y0+wid-4, clamped;
    //      zero-filled via src_size=0 when out of range), lane -> xx=4+4*lane.
    const int  y2    = y0 + wid - 4;
    const int  yc    = y2 < 0 ? 0 : (y2 > H_ - 1 ? H_ - 1 : y2);
    const int  rsz   = ((unsigned)y2 < (unsigned)H_) ? 16 : 0;
    ull st_run = (ull)__cvta_generic_to_global(
                     in2 + ((long)(b * C_)) * HW_ + (long)yc * W_ + x0);
    const uint32_t st_dst =
        (uint32_t)__cvta_generic_to_shared(&s2[0][0][wid][4 + x0]);
    const uint32_t CCB  = NDY * W2 * 4;            // 4896  (cc stride)
    const uint32_t BUFB = CC * NDY * W2 * 4;       // 19584 (buffer stride)
    const ull      HWB  = (ull)HW_ * sizeof(float);

#define STAGE(bufsel)                                                         \
    {                                                                         \
        _Pragma("unroll")                                                     \
        for (int cc = 0; cc < CC; cc++)                                       \
            cp16(st_dst + (bufsel) * BUFB + cc * CCB,                         \
                 st_run + (ull)cc * HWB, rsz);                                \
        asm volatile("cp.async.commit_group;" ::: "memory");                  \
        st_run += (ull)CC * HWB;                                              \
    }

    // ---- prologue: chunk 0 -> buffer 0 ----
    STAGE(0u);
    asm volatile("cp.async.wait_group 0;" ::: "memory");
    __syncthreads();

    float acc[NDY][4];                     // [dx][px]
#pragma unroll
    for (int d = 0; d < NDY; d++)
#pragma unroll
        for (int i = 0; i < 4; i++) acc[d][i] = 0.0f;

    const float* a_run = in1 + ((long)(b * C_)) * HW_ + (long)y0 * W_ + x0;
    uint32_t buf = 0;

    for (int c0 = 0; c0 < C_; c0 += CC) {
        const bool has_next = (c0 + CC < C_);
        if (has_next) STAGE(buf ^ 1u);

#pragma unroll
        for (int cc = 0; cc < CC; cc++) {
            float4 a = *reinterpret_cast<const float4*>(a_run + (long)cc * HW_);
            const float* sr = &s2[buf][cc][wid][x0];       // 16B aligned
            float4 w0 = *reinterpret_cast<const float4*>(sr);
            float4 w1 = *reinterpret_cast<const float4*>(sr + 4);
            float4 w2 = *reinterpret_cast<const float4*>(sr + 8);
            float wv[12] = {w0.x, w0.y, w0.z, w0.w,
                            w1.x, w1.y, w1.z, w1.w,
                            w2.x, w2.y, w2.z, w2.w};
            float av[4] = {a.x, a.y, a.z, a.w};
#pragma unroll
            for (int d = 0; d < NDY; d++)
#pragma unroll
                for (int i = 0; i < 4; i++)
                    acc[d][i] = fmaf(av[i], wv[i + d], acc[d][i]);
        }
        a_run += (long)CC * HW_;

        if (has_next)
            asm volatile("cp.async.wait_group 0;" ::: "memory");
        __syncthreads();
        buf ^= 1u;
    }

    // ---- epilogue: 9 float4 stores (out channels wid*9 .. wid*9+8) ----
    const float sc = 1.0f / (float)C_;
    float* ob = out + (((long)b * 81 + wid * NDY) * H_ + y0) * (long)W_ + x0;
#pragma unroll
    for (int d = 0; d < NDY; d++) {
        float4 v = make_float4(acc[d][0] * sc, acc[d][1] * sc,
                               acc[d][2] * sc, acc[d][3] * sc);
        *reinterpret_cast<float4*>(ob + (long)d * HW_) = v;
    }
}

extern "C" void kernel_launch(void* const* d_in, const int* in_sizes, int n_in,
                              void* d_out, int out_size)
{
    const float* in1 = (const float*)d_in[0];
    const float* in2 = (const float*)d_in[1];
    float* out = (float*)d_out;

    dim3 grid(H_, B_);     // one block per (output row, batch)
    dim3 block(NTHR);      // 9 warps: warp = dy
    corr_kernel<<<grid, block>>>(in1, in2, out);
}